// round 14
// baseline (speedup 1.0000x reference)
#include <cuda_runtime.h>
#include <cuda_fp16.h>
#include <cstdint>
#include <math.h>

#define N_TASKS 8192
#define EDIM 64
#define DDIM 64
#define BB 2
#define NT 32           // i-tiles per CTA (half of N / 128)
#define LEAK 0.7f

// ---------------- device scratch (no runtime allocation) -------------------
__device__ __half g_Uh[N_TASKS * EDIM];            // fp16 U  [i][e]
__device__ __half g_Vh[N_TASKS * EDIM];            // fp16 V=U@W  [i][e]
__device__ __half g_Et[BB * DDIM * N_TASKS];       // fp16 gated states^T [b][d][i]

// ---------------- PTX helpers ----------------------------------------------
__device__ __forceinline__ uint32_t smem_u32(const void* p) {
    uint32_t a;
    asm("{ .reg .u64 t; cvta.to.shared.u64 t, %1; cvt.u32.u64 %0, t; }" : "=r"(a) : "l"(p));
    return a;
}
__device__ __forceinline__ void cp16(uint32_t dst, const void* src) {
    asm volatile("cp.async.ca.shared.global [%0], [%1], 16;" :: "r"(dst), "l"(src) : "memory");
}
__device__ __forceinline__ void cp_commit() {
    asm volatile("cp.async.commit_group;" ::: "memory");
}
__device__ __forceinline__ void ldsm4(uint32_t& r0, uint32_t& r1, uint32_t& r2, uint32_t& r3,
                                      uint32_t addr) {
    asm volatile("ldmatrix.sync.aligned.m8n8.x4.shared.b16 {%0,%1,%2,%3}, [%4];"
                 : "=r"(r0), "=r"(r1), "=r"(r2), "=r"(r3) : "r"(addr));
}
__device__ __forceinline__ void mma16816(float* d, const uint32_t* a, uint32_t b0, uint32_t b1) {
    asm volatile("mma.sync.aligned.m16n8k16.row.col.f32.f16.f16.f32 "
                 "{%0,%1,%2,%3}, {%4,%5,%6,%7}, {%8,%9}, {%0,%1,%2,%3};"
                 : "+f"(d[0]), "+f"(d[1]), "+f"(d[2]), "+f"(d[3])
                 : "r"(a[0]), "r"(a[1]), "r"(a[2]), "r"(a[3]), "r"(b0), "r"(b1));
}
__device__ __forceinline__ uint32_t packh2(float lo, float hi) {
    uint32_t r;
    asm("cvt.rn.f16x2.f32 %0, %1, %2;" : "=r"(r) : "f"(hi), "f"(lo));
    return r;
}
// sigmoid(x + b) = 0.5*tanh(0.5*x + 0.5*b) + 0.5   (1 MUFU, no div)
__device__ __forceinline__ float sigm_t(float x, float bh) {
    float y;
    asm("tanh.approx.f32 %0, %1;" : "=f"(y) : "f"(fmaf(x, 0.5f, bh)));
    return fmaf(y, 0.5f, 0.5f);
}
__device__ __forceinline__ void red2(float* dst, float a, float b) {
    asm volatile("red.global.add.v2.f32 [%0], {%1, %2};" :: "l"(dst), "f"(a), "f"(b) : "memory");
}
__device__ __forceinline__ void sts32(uint32_t addr, uint32_t v) {
    asm volatile("st.shared.b32 [%0], %1;" :: "r"(addr), "r"(v) : "memory");
}

// SMEM layout (bytes). U/V rows 144B stride, E/P rows 272B stride.
#define SM_U   0
#define SM_V0  18432
#define VSTG   18432
#define SM_E0  (SM_V0 + 2 * VSTG)        // 55296
#define ESTG   34816
#define SM_P   (SM_E0 + 2 * ESTG)        // 124928
#define SMEM_TOTAL (SM_P + 34816)        // 159744

// ---------------------------------------------------------------------------
// Fused prep: blocks [0,128): V = U@W + fp16 casts.  blocks [128,256):
// Et[b][d][i] = fp16(states * relu(prof-LEAK)); also writes out = states.
// ---------------------------------------------------------------------------
__global__ void __launch_bounds__(256) prep_all_kernel(
    const float* __restrict__ U, const float* __restrict__ W,
    const float* __restrict__ states, const float* __restrict__ prof,
    float* __restrict__ out)
{
    __shared__ float sW[EDIM][EDIM + 1];
    __shared__ float sU[64][EDIM + 1];
    __shared__ __half st[DDIM][136];
    const int t = threadIdx.x;

    if (blockIdx.x < 128) {
        const int blk = blockIdx.x;
        for (int idx = t; idx < EDIM * EDIM; idx += 256)
            sW[idx / EDIM][idx % EDIM] = W[idx];
        for (int idx = t; idx < 64 * EDIM; idx += 256) {
            int r = idx / EDIM, e = idx % EDIM;
            sU[r][e] = U[(blk * 64 + r) * EDIM + e];
        }
        __syncthreads();
        const int i = t / 4, f0 = (t % 4) * 16;
        float acc[16];
#pragma unroll
        for (int k = 0; k < 16; k++) acc[k] = 0.f;
        for (int e = 0; e < EDIM; e++) {
            float u = sU[i][e];
#pragma unroll
            for (int k = 0; k < 16; k++) acc[k] = fmaf(u, sW[e][f0 + k], acc[k]);
        }
#pragma unroll
        for (int k = 0; k < 16; k++)
            g_Vh[(blk * 64 + i) * EDIM + f0 + k] = __float2half(acc[k]);
        for (int idx = t; idx < 64 * EDIM; idx += 256) {
            int r = idx / EDIM, e = idx % EDIM;
            g_Uh[(blk * 64 + r) * EDIM + e] = __float2half(sU[r][e]);
        }
    } else {
        const int bi = (blockIdx.x - 128) & 63;
        const int b  = (blockIdx.x - 128) >> 6;
        for (int idx = t; idx < 128 * 16; idx += 256) {
            int il = idx >> 4, d4 = idx & 15;
            int ig = bi * 128 + il;
            float g = prof[b * N_TASKS + ig] - LEAK;
            g = g > 0.f ? g : 0.f;
            size_t off = ((size_t)b * N_TASKS + ig) * DDIM + d4 * 4;
            float4 s4 = *(const float4*)&states[off];
            *(float4*)&out[off] = s4;          // out = states (replaces memcpy)
            st[d4 * 4 + 0][il] = __float2half(s4.x * g);
            st[d4 * 4 + 1][il] = __float2half(s4.y * g);
            st[d4 * 4 + 2][il] = __float2half(s4.z * g);
            st[d4 * 4 + 3][il] = __float2half(s4.w * g);
        }
        __syncthreads();
        for (int idx = t; idx < 64 * 16; idx += 256) {
            int d = idx >> 4, ch = idx & 15;
            *(uint4*)&g_Et[((size_t)b * DDIM + d) * N_TASKS + bi * 128 + ch * 8] =
                *(const uint4*)&st[d][ch * 8];
        }
    }
}

// ---------------------------------------------------------------------------
// Main kernel: warp = (j-strip of 32, i-half of 64). Phase A M=32; phase B
// M=32, one batch per warp, k=128 with own-half P in regs + partner via SMEM.
// Grid: (64 j-tiles, 2 i-halves), 256 threads (8 warps).
// ---------------------------------------------------------------------------
__global__ void __launch_bounds__(256, 1) mma_transfer_kernel(
    const float* __restrict__ bias_ptr, float* __restrict__ out)
{
    extern __shared__ char smem[];
    const uint32_t sb = smem_u32(smem);
    const int t = threadIdx.x, w = t >> 5, lane = t & 31;
    const int s = w & 3;            // j-strip (32 rows)
    const int g = w >> 2;           // i-half (phase A) and batch (phase B)
    const int jt = blockIdx.x, half_id = blockIdx.y;
    const float bh = 0.5f * bias_ptr[0];
    const int lr = lane & 7, lg = lane >> 3;
    const int qrow = lane >> 2, qcol = (lane & 3) * 2;

    // ---- issue tile-0 loads (cp.async) ----
    {
        const __half* vsrc = g_Vh + ((size_t)half_id * 4096) * 64;
        for (int c = t; c < 1024; c += 256) {
            int r = c >> 3, ch = c & 7;
            cp16(sb + SM_V0 + r * 144 + ch * 16, vsrc + r * 64 + ch * 8);
        }
        const size_t ib = (size_t)half_id * 4096;
        for (int c = t; c < 2048; c += 256) {
            int b = c >> 10, rem = c & 1023;
            int d = rem >> 4, ch = rem & 15;
            cp16(sb + SM_E0 + b * 17408 + d * 272 + ch * 16,
                 g_Et + ((size_t)(b * 64 + d)) * N_TASKS + ib + ch * 8);
        }
        cp_commit();
    }

    // ---- U tile -> SMEM, then persistent A-fragments (32 rows per warp) ----
    for (int c = t; c < 1024; c += 256) {
        int r = c >> 3, ch = c & 7;
        *(uint4*)(smem + SM_U + r * 144 + ch * 16) =
            *(const uint4*)(g_Uh + ((size_t)(jt * 128 + r)) * 64 + ch * 8);
    }
    __syncthreads();
    uint32_t uf[2][4][4];
#pragma unroll
    for (int jb = 0; jb < 2; jb++)
#pragma unroll
        for (int kc = 0; kc < 4; kc++) {
            int row = s * 32 + jb * 16 + (lg & 1) * 8 + lr;
            int col = kc * 16 + (lg >> 1) * 8;
            ldsm4(uf[jb][kc][0], uf[jb][kc][1], uf[jb][kc][2], uf[jb][kc][3],
                  sb + SM_U + row * 144 + col * 2);
        }

    float accL[2][8][4];
#pragma unroll
    for (int jb = 0; jb < 2; jb++)
#pragma unroll
        for (int nb = 0; nb < 8; nb++)
#pragma unroll
            for (int c = 0; c < 4; c++) accL[jb][nb][c] = 0.f;

    const int diag_it = ((jt >> 5) == half_id) ? (jt & 31) : -1;

    for (int it = 0; it < NT; it++) {
        __syncthreads();
        if (it + 1 < NT) {
            const int nt = it + 1;
            const __half* vsrc = g_Vh + ((size_t)(half_id * 4096 + nt * 128)) * 64;
            const uint32_t vdst = sb + SM_V0 + (nt & 1) * VSTG;
            for (int c = t; c < 1024; c += 256) {
                int r = c >> 3, ch = c & 7;
                cp16(vdst + r * 144 + ch * 16, vsrc + r * 64 + ch * 8);
            }
            const size_t ib = (size_t)half_id * 4096 + (size_t)nt * 128;
            const uint32_t edst = sb + SM_E0 + (nt & 1) * ESTG;
            for (int c = t; c < 2048; c += 256) {
                int b = c >> 10, rem = c & 1023;
                int d = rem >> 4, ch = rem & 15;
                cp16(edst + b * 17408 + d * 272 + ch * 16,
                     g_Et + ((size_t)(b * 64 + d)) * N_TASKS + ib + ch * 8);
            }
            cp_commit();
            asm volatile("cp.async.wait_group 1;" ::: "memory");
        } else {
            asm volatile("cp.async.wait_group 0;" ::: "memory");
        }
        __syncthreads();

        const uint32_t vbase = sb + SM_V0 + (it & 1) * VSTG;
        const uint32_t ebase = sb + SM_E0 + (it & 1) * ESTG + g * 17408;

        // ---- Phase A: S(32j x 64i own half), M=32 reuses each V-frag 2x ----
        float accS[2][8][4];
#pragma unroll
        for (int jb = 0; jb < 2; jb++)
#pragma unroll
            for (int nb = 0; nb < 8; nb++)
#pragma unroll
                for (int c = 0; c < 4; c++) accS[jb][nb][c] = 0.f;
#pragma unroll
        for (int kc = 0; kc < 4; kc++)
#pragma unroll
            for (int nb4 = 0; nb4 < 4; nb4++) {
                uint32_t b0, b1, b2, b3;
                int row = g * 64 + nb4 * 16 + (lg >> 1) * 8 + lr;
                int col = kc * 16 + (lg & 1) * 8;
                ldsm4(b0, b1, b2, b3, vbase + row * 144 + col * 2);
                mma16816(accS[0][nb4 * 2],     uf[0][kc], b0, b1);
                mma16816(accS[0][nb4 * 2 + 1], uf[0][kc], b2, b3);
                mma16816(accS[1][nb4 * 2],     uf[1][kc], b0, b1);
                mma16816(accS[1][nb4 * 2 + 1], uf[1][kc], b2, b3);
            }

        // ---- sigmoid + diag mask + pack; keep own A-frags, STS P ----
        uint32_t pf[2][4][4];
#pragma unroll
        for (int jb = 0; jb < 2; jb++) {
            const int jl = s * 32 + jb * 16 + qrow;
#pragma unroll
            for (int nb = 0; nb < 8; nb++) {
                float p0 = sigm_t(accS[jb][nb][0], bh);
                float p1 = sigm_t(accS[jb][nb][1], bh);
                float p2 = sigm_t(accS[jb][nb][2], bh);
                float p3 = sigm_t(accS[jb][nb][3], bh);
                const int i0 = g * 64 + nb * 8 + qcol;
                if (it == diag_it) {
                    if (i0 == jl)         p0 = 0.f;
                    if (i0 + 1 == jl)     p1 = 0.f;
                    if (i0 == jl + 8)     p2 = 0.f;
                    if (i0 + 1 == jl + 8) p3 = 0.f;
                }
                uint32_t lo = packh2(p0, p1);
                uint32_t hi = packh2(p2, p3);
                pf[jb][nb >> 1][(nb & 1) * 2 + 0] = lo;
                pf[jb][nb >> 1][(nb & 1) * 2 + 1] = hi;
                uint32_t pa = sb + SM_P + jl * 272 + i0 * 2;
                sts32(pa, lo);
                sts32(pa + 8 * 272, hi);
            }
        }

        // ---- Phase B own half (k = own 64i) — hides the P-exchange bar ----
#pragma unroll
        for (int kc = 0; kc < 4; kc++)
#pragma unroll
            for (int db = 0; db < 4; db++) {
                uint32_t e0, e1, e2, e3;
                int row = db * 16 + (lg >> 1) * 8 + lr;
                int col = g * 64 + kc * 16 + (lg & 1) * 8;
                ldsm4(e0, e1, e2, e3, ebase + row * 272 + col * 2);
                mma16816(accL[0][db * 2],     pf[0][kc], e0, e1);
                mma16816(accL[0][db * 2 + 1], pf[0][kc], e2, e3);
                mma16816(accL[1][db * 2],     pf[1][kc], e0, e1);
                mma16816(accL[1][db * 2 + 1], pf[1][kc], e2, e3);
            }

        __syncthreads();   // all P strips visible

        // ---- Phase B partner half (P via ldsm from SMEM) ----
        const int go = g ^ 1;
#pragma unroll
        for (int kc = 0; kc < 4; kc++) {
            uint32_t q0[4], q1[4];
            {
                int col = go * 64 + kc * 16 + (lg >> 1) * 8;
                int r0 = s * 32 + (lg & 1) * 8 + lr;
                ldsm4(q0[0], q0[1], q0[2], q0[3], sb + SM_P + r0 * 272 + col * 2);
                ldsm4(q1[0], q1[1], q1[2], q1[3], sb + SM_P + (r0 + 16) * 272 + col * 2);
            }
#pragma unroll
            for (int db = 0; db < 4; db++) {
                uint32_t e0, e1, e2, e3;
                int row = db * 16 + (lg >> 1) * 8 + lr;
                int col = go * 64 + kc * 16 + (lg & 1) * 8;
                ldsm4(e0, e1, e2, e3, ebase + row * 272 + col * 2);
                mma16816(accL[0][db * 2],     q0, e0, e1);
                mma16816(accL[0][db * 2 + 1], q0, e2, e3);
                mma16816(accL[1][db * 2],     q1, e0, e1);
                mma16816(accL[1][db * 2 + 1], q1, e2, e3);
            }
        }
    }

    // ---- accumulate into out (pre-initialized to states by prep) ----
#pragma unroll
    for (int jb = 0; jb < 2; jb++) {
        const int j0 = jt * 128 + s * 32 + jb * 16 + qrow;
#pragma unroll
        for (int nb = 0; nb < 8; nb++) {
            float* dst = out + ((size_t)g * N_TASKS + j0) * DDIM + nb * 8 + qcol;
            red2(dst,            accL[jb][nb][0], accL[jb][nb][1]);
            red2(dst + 8 * DDIM, accL[jb][nb][2], accL[jb][nb][3]);
        }
    }
}

// ---------------------------------------------------------------------------
extern "C" void kernel_launch(void* const* d_in, const int* in_sizes, int n_in,
                              void* d_out, int out_size)
{
    const float* states = (const float*)d_in[0];   // [2, 8192, 64]
    const float* prof   = (const float*)d_in[1];   // [2, 8192]
    const float* U      = (const float*)d_in[2];   // [8192, 64]
    const float* W      = (const float*)d_in[3];   // [1, 64, 64]
    const float* bias   = (const float*)d_in[4];   // [1]
    float* out          = (float*)d_out;           // [2, 8192, 64]

    cudaFuncSetAttribute(mma_transfer_kernel,
                         cudaFuncAttributeMaxDynamicSharedMemorySize, SMEM_TOTAL);

    prep_all_kernel<<<256, 256>>>(U, W, states, prof, out);
    mma_transfer_kernel<<<dim3(N_TASKS / 128, 2), 256, SMEM_TOTAL>>>(bias, out);
}